// round 8
// baseline (speedup 1.0000x reference)
#include <cuda_runtime.h>
#include <cuda_bf16.h>
#include <math.h>

#define N_ENTITY 64368
#define N_REL    46
#define NBASES   8
#define DDIM     128
#define E_EDGES  600000
#define B_USERS  64
#define L_CTX    50
#define NE_ENT   256

#define PREP_THREADS 1024
#define CHUNK        63                       // 1024*63 = 64512 >= N_ENTITY
#define HPAD         (PREP_THREADS * CHUNK)   // 64512
#define MMAX         4096                     // >= B*L + NE = 3456

// ---- device-global scratch (allocation forbidden; int atomics only) ----
__device__ int   g_flag[HPAD];             // needed-entity flags (0/1)
__device__ int   g_slot[N_ENTITY];         // entity -> compact slot (-1 if unused)
__device__ int   g_ent[MMAX];              // slot -> entity
__device__ int   g_M;                      // number of used slots
__device__ int   g_hist2[MMAX];            // relevant edges per slot
__device__ int   g_eoff[MMAX + 1];         // slot-sorted edge offsets
__device__ int   g_cur2[MMAX];             // scatter cursors
__device__ int   g_deg2[MMAX * N_REL];     // per-(slot,rel) degree
__device__ int   g_elist[E_EDGES];         // slot-sorted edges: src | (rel<<17)
__device__ __align__(16) float g_kgc[MMAX * DDIM];  // 2 MB compact kg_emb
__device__ float g_sent[MMAX];             // per-slot attention score

// ---------------------------------------------------------------------------
// zero flags, hist, deg
// ---------------------------------------------------------------------------
__global__ void k_setup() {
    const int stride = gridDim.x * blockDim.x;
    const int tid = blockIdx.x * blockDim.x + threadIdx.x;
    for (int i = tid; i < HPAD; i += stride) g_flag[i] = 0;
    for (int i = tid; i < MMAX; i += stride) g_hist2[i] = 0;
    for (int i = tid; i < MMAX * N_REL; i += stride) g_deg2[i] = 0;
}

// ---------------------------------------------------------------------------
// single block: mark needed entities, then scan flags -> slots (+reverse map)
// ---------------------------------------------------------------------------
__global__ void __launch_bounds__(PREP_THREADS) k_prep(const int* __restrict__ ctx,
                                                       const int* __restrict__ entity_ids) {
    __shared__ int sh[PREP_THREADS];
    int t = threadIdx.x;

    // mark (writes ordered by __syncthreads within this single block)
    for (int i = t; i < B_USERS * L_CTX; i += PREP_THREADS) g_flag[ctx[i]] = 1;
    for (int i = t; i < NE_ENT; i += PREP_THREADS)          g_flag[entity_ids[i]] = 1;
    __syncthreads();

    // per-thread chunk sums
    int base = t * CHUNK;
    int v[CHUNK];
    int sum = 0;
#pragma unroll
    for (int j = 0; j < CHUNK; j++) { v[j] = g_flag[base + j]; sum += v[j]; }
    sh[t] = sum;
    __syncthreads();
    // Hillis-Steele inclusive scan of 1024 partials
    for (int o = 1; o < PREP_THREADS; o <<= 1) {
        int a = (t >= o) ? sh[t - o] : 0;
        __syncthreads();
        sh[t] += a;
        __syncthreads();
    }
    int excl = sh[t] - sum;
#pragma unroll
    for (int j = 0; j < CHUNK; j++) {
        int i = base + j;
        if (i < N_ENTITY) {
            if (v[j]) { g_slot[i] = excl; g_ent[excl] = i; }
            else        g_slot[i] = -1;
        }
        excl += v[j];
    }
    if (t == PREP_THREADS - 1) g_M = sh[PREP_THREADS - 1];
}

// ---------------------------------------------------------------------------
// edge pass 1: hist + degree for edges into needed dsts
// ---------------------------------------------------------------------------
__global__ void k_epass1(const int* __restrict__ edge_index, const int* __restrict__ edge_type) {
    int e = blockIdx.x * blockDim.x + threadIdx.x;
    if (e >= E_EDGES) return;
    int dst = edge_index[E_EDGES + e];
    int s = g_slot[dst];
    if (s < 0) return;
    int rel = edge_type[e];
    atomicAdd(&g_hist2[s], 1);
    atomicAdd(&g_deg2[s * N_REL + rel], 1);
}

// ---------------------------------------------------------------------------
// slot-edge scan: 1 block, 1024 threads, 4 elements each over MMAX=4096
// ---------------------------------------------------------------------------
__global__ void k_escan() {
    __shared__ int sh[1024];
    int t = threadIdx.x;
    int v[4]; int sum = 0;
#pragma unroll
    for (int j = 0; j < 4; j++) { v[j] = g_hist2[t * 4 + j]; sum += v[j]; }
    sh[t] = sum;
    __syncthreads();
    for (int o = 1; o < 1024; o <<= 1) {
        int a = (t >= o) ? sh[t - o] : 0;
        __syncthreads();
        sh[t] += a;
        __syncthreads();
    }
    int excl = sh[t] - sum;
#pragma unroll
    for (int j = 0; j < 4; j++) {
        g_eoff[t * 4 + j] = excl;
        g_cur2[t * 4 + j] = excl;
        excl += v[j];
    }
    if (t == 1023) g_eoff[MMAX] = excl;
}

// ---------------------------------------------------------------------------
// edge pass 2: scatter relevant edges into slot-sorted order
// ---------------------------------------------------------------------------
__global__ void k_epass2(const int* __restrict__ edge_index, const int* __restrict__ edge_type) {
    int e = blockIdx.x * blockDim.x + threadIdx.x;
    if (e >= E_EDGES) return;
    int dst = edge_index[E_EDGES + e];
    int s = g_slot[dst];
    if (s < 0) return;
    int src = edge_index[e];
    int rel = edge_type[e];
    int pos = atomicAdd(&g_cur2[s], 1);
    g_elist[pos] = src | (rel << 17);       // src < 2^17, rel < 2^6
}

// ---------------------------------------------------------------------------
// aggregation: warp per needed slot; gather basis rows directly.
// kg = root + bias + sum_edges norm * sum_b comp[rel,b] * basis[b][src]
// ---------------------------------------------------------------------------
__global__ void __launch_bounds__(256) k_agg(const float* __restrict__ basis,
                                             const float* __restrict__ comp,
                                             const float* __restrict__ root,
                                             const float* __restrict__ bias) {
    __shared__ float s_comp[N_REL * NBASES];
    for (int i = threadIdx.x; i < N_REL * NBASES; i += blockDim.x) s_comp[i] = comp[i];
    __syncthreads();

    int slot = (blockIdx.x * blockDim.x + threadIdx.x) >> 5;
    int lane = threadIdx.x & 31;
    if (slot >= g_M) return;

    int ent = g_ent[slot];
    float4 acc = reinterpret_cast<const float4*>(root)[(size_t)ent * 32 + lane];
    float4 bv  = reinterpret_cast<const float4*>(bias)[lane];
    acc.x += bv.x; acc.y += bv.y; acc.z += bv.z; acc.w += bv.w;

    int n0 = g_eoff[slot], n1 = g_eoff[slot + 1];
    for (int i = n0; i < n1; i++) {
        int packed = g_elist[i];                 // warp-broadcast load
        int src = packed & 0x1FFFF;
        int rel = packed >> 17;
        float norm = 1.0f / (float)max(g_deg2[slot * N_REL + rel], 1);
        const float* c = s_comp + rel * NBASES;
        const float4* bp = reinterpret_cast<const float4*>(basis) + (size_t)src * 32 + lane;
        float4 br[NBASES];
#pragma unroll
        for (int b = 0; b < NBASES; b++) br[b] = bp[(size_t)b * (N_ENTITY * 32)];
        float4 m;
        m.x = c[0] * br[0].x; m.y = c[0] * br[0].y; m.z = c[0] * br[0].z; m.w = c[0] * br[0].w;
#pragma unroll
        for (int b = 1; b < NBASES; b++) {
            float cb = c[b];
            m.x += cb * br[b].x; m.y += cb * br[b].y; m.z += cb * br[b].z; m.w += cb * br[b].w;
        }
        acc.x += norm * m.x; acc.y += norm * m.y; acc.z += norm * m.z; acc.w += norm * m.w;
    }
    reinterpret_cast<float4*>(g_kgc)[(size_t)slot * 32 + lane] = acc;
}

// ---------------------------------------------------------------------------
// attention score PER SLOT (score depends only on the entity embedding):
//   g_sent[slot] = sum_d tanh((kgc[slot] @ W)[d]) * ab[d]
// one warp per slot
// ---------------------------------------------------------------------------
__global__ void __launch_bounds__(256) k_score(const float* __restrict__ attn_W,
                                               const float* __restrict__ attn_b) {
    int slot = (blockIdx.x * blockDim.x + threadIdx.x) >> 5;
    int lane = threadIdx.x & 31;
    if (slot >= g_M) return;

    float4 h4 = reinterpret_cast<const float4*>(g_kgc + (size_t)slot * DDIM)[lane];

    float u0 = 0.f, u1 = 0.f, u2 = 0.f, u3 = 0.f;
#pragma unroll 4
    for (int k = 0; k < DDIM; k++) {
        int sl = k >> 2, cp = k & 3;
        float hv = (cp == 0) ? h4.x : (cp == 1) ? h4.y : (cp == 2) ? h4.z : h4.w;
        float hk = __shfl_sync(0xFFFFFFFFu, hv, sl);
        const float* wr = attn_W + k * DDIM;
        u0 += hk * wr[lane];
        u1 += hk * wr[lane + 32];
        u2 += hk * wr[lane + 64];
        u3 += hk * wr[lane + 96];
    }
    float acc = tanhf(u0) * attn_b[lane] + tanhf(u1) * attn_b[lane + 32]
              + tanhf(u2) * attn_b[lane + 64] + tanhf(u3) * attn_b[lane + 96];
#pragma unroll
    for (int o = 16; o; o >>= 1) acc += __shfl_xor_sync(0xFFFFFFFFu, acc, o);
    if (lane == 0) g_sent[slot] = acc;
}

// ---------------------------------------------------------------------------
// fused output kernel: blocks [0,64) = users, [64,320) = entities
// ---------------------------------------------------------------------------
__global__ void __launch_bounds__(DDIM) k_out(const int* __restrict__ ctx,
                       const int* __restrict__ cmask,
                       const int* __restrict__ entity_ids,
                       const float* __restrict__ fc1_W, const float* __restrict__ fc1_b,
                       const float* __restrict__ fc2_W, const float* __restrict__ fc2_b,
                       const float* __restrict__ efc1_W, const float* __restrict__ efc1_b,
                       const float* __restrict__ efc2_W, const float* __restrict__ efc2_b,
                       float* __restrict__ out) {
    __shared__ float xin[DDIM];
    __shared__ float yv[DDIM];
    __shared__ float attn[L_CTX];
    int t = threadIdx.x;

    const float *W1, *b1, *W2, *b2;
    float* dst;

    if (blockIdx.x < B_USERS) {
        int b = blockIdx.x;
        // softmax over masked per-slot scores (serial, 50 elems)
        if (t == 0) {
            float mx = -3.4e38f; bool any = false;
            float scl[L_CTX];
            for (int l = 0; l < L_CTX; l++) {
                scl[l] = g_sent[g_slot[ctx[b * L_CTX + l]]];
                if (cmask[b * L_CTX + l]) { any = true; mx = fmaxf(mx, scl[l]); }
            }
            float s = 0.f;
            for (int l = 0; l < L_CTX; l++) {
                float v = cmask[b * L_CTX + l] ? expf(scl[l] - mx) : 0.f;
                attn[l] = v; s += v;
            }
            float inv = any ? 1.f / s : 0.f;
            for (int l = 0; l < L_CTX; l++) attn[l] *= inv;
        }
        __syncthreads();
        // user_rep[t] = sum_l attn[l] * kgc[slot_l][t]
        // L_CTX = 50 is even: the pair loop covers ALL l (no tail!)
        float r0 = 0.f, r1 = 0.f;
        for (int l = 0; l < L_CTX; l += 2) {
            int s0 = g_slot[ctx[b * L_CTX + l]];
            int s1 = g_slot[ctx[b * L_CTX + l + 1]];
            r0 += attn[l]     * g_kgc[(size_t)s0 * DDIM + t];
            r1 += attn[l + 1] * g_kgc[(size_t)s1 * DDIM + t];
        }
        xin[t] = r0 + r1;
        W1 = fc1_W; b1 = fc1_b; W2 = fc2_W; b2 = fc2_b;
        dst = out + b * DDIM;
    } else {
        int i = blockIdx.x - B_USERS;
        int slot = g_slot[entity_ids[i]];
        xin[t] = g_kgc[(size_t)slot * DDIM + t];
        W1 = efc1_W; b1 = efc1_b; W2 = efc2_W; b2 = efc2_b;
        dst = out + B_USERS * DDIM + i * DDIM;
    }
    __syncthreads();

    // y = relu(x @ W1 + b1)  with 4 accumulators
    float y0 = 0.f, y1 = 0.f, y2 = 0.f, y3 = 0.f;
#pragma unroll 4
    for (int k = 0; k < DDIM; k += 4) {
        y0 += xin[k]     * W1[(k)     * DDIM + t];
        y1 += xin[k + 1] * W1[(k + 1) * DDIM + t];
        y2 += xin[k + 2] * W1[(k + 2) * DDIM + t];
        y3 += xin[k + 3] * W1[(k + 3) * DDIM + t];
    }
    yv[t] = fmaxf(b1[t] + (y0 + y1) + (y2 + y3), 0.f);
    __syncthreads();

    float o0 = 0.f, o1 = 0.f, o2 = 0.f, o3 = 0.f;
#pragma unroll 4
    for (int k = 0; k < DDIM; k += 4) {
        o0 += yv[k]     * W2[(k)     * DDIM + t];
        o1 += yv[k + 1] * W2[(k + 1) * DDIM + t];
        o2 += yv[k + 2] * W2[(k + 2) * DDIM + t];
        o3 += yv[k + 3] * W2[(k + 3) * DDIM + t];
    }
    dst[t] = b2[t] + (o0 + o1) + (o2 + o3);
}

// ---------------------------------------------------------------------------
extern "C" void kernel_launch(void* const* d_in, const int* in_sizes, int n_in,
                              void* d_out, int out_size) {
    const int*   edge_index = (const int*)d_in[0];
    const int*   edge_type  = (const int*)d_in[1];
    const int*   ctx        = (const int*)d_in[2];
    const int*   cmask      = (const int*)d_in[3];
    const int*   entity_ids = (const int*)d_in[4];
    const float* comp       = (const float*)d_in[5];
    const float* basis      = (const float*)d_in[6];
    const float* root       = (const float*)d_in[7];
    const float* bias       = (const float*)d_in[8];
    const float* attn_W     = (const float*)d_in[9];
    const float* attn_b     = (const float*)d_in[10];
    const float* fc1_W      = (const float*)d_in[11];
    const float* fc1_b      = (const float*)d_in[12];
    const float* fc2_W      = (const float*)d_in[13];
    const float* fc2_b      = (const float*)d_in[14];
    const float* efc1_W     = (const float*)d_in[15];
    const float* efc1_b     = (const float*)d_in[16];
    const float* efc2_W     = (const float*)d_in[17];
    const float* efc2_b     = (const float*)d_in[18];
    float* out = (float*)d_out;

    k_setup<<<256, 256>>>();
    k_prep<<<1, PREP_THREADS>>>(ctx, entity_ids);
    k_epass1<<<(E_EDGES + 255) / 256, 256>>>(edge_index, edge_type);
    k_escan<<<1, 1024>>>();
    k_epass2<<<(E_EDGES + 255) / 256, 256>>>(edge_index, edge_type);
    k_agg<<<(MMAX * 32) / 256, 256>>>(basis, comp, root, bias);
    k_score<<<(MMAX * 32) / 256, 256>>>(attn_W, attn_b);
    k_out<<<B_USERS + NE_ENT, DDIM>>>(ctx, cmask, entity_ids,
                                      fc1_W, fc1_b, fc2_W, fc2_b,
                                      efc1_W, efc1_b, efc2_W, efc2_b, out);
}

// round 9
// speedup vs baseline: 1.6187x; 1.6187x over previous
#include <cuda_runtime.h>
#include <cuda_bf16.h>
#include <math.h>

#define N_ENTITY 64368
#define N_REL    46
#define NBASES   8
#define DDIM     128
#define E_EDGES  600000
#define B_USERS  64
#define L_CTX    50
#define NE_ENT   256

#define NCAND    (B_USERS * L_CTX + NE_ENT)   // 3456 candidate ids
#define MMAX     4096                          // > NCAND

// ---- device-global scratch (allocation forbidden; int atomics only) ----
__device__ int   g_slot[N_ENTITY];         // entity -> compact slot (-1 if unused)
__device__ int   g_ent[MMAX];              // slot -> entity
__device__ int   g_M;                      // number of used slots
__device__ int   g_hist2[MMAX];            // relevant edges per slot
__device__ int   g_eoff[MMAX + 1];         // slot-sorted edge offsets
__device__ int   g_cur2[MMAX];             // scatter cursors
__device__ int   g_deg2[MMAX * N_REL];     // per-(slot,rel) degree
__device__ int   g_elist[E_EDGES];         // slot-sorted edges: src | (rel<<17)
__device__ __align__(16) float g_kgc[MMAX * DDIM];  // 2 MB compact kg_emb
__device__ float g_sent[MMAX];             // per-slot attention score

// ---------------------------------------------------------------------------
// setup: slot = -1, zero hist/deg, reset slot counter
// ---------------------------------------------------------------------------
__global__ void k_setup() {
    const int stride = gridDim.x * blockDim.x;
    const int tid = blockIdx.x * blockDim.x + threadIdx.x;
    for (int i = tid; i < N_ENTITY; i += stride) g_slot[i] = -1;
    for (int i = tid; i < MMAX; i += stride) g_hist2[i] = 0;
    for (int i = tid; i < MMAX * N_REL; i += stride) g_deg2[i] = 0;
    if (tid == 0) g_M = 0;
}

// ---------------------------------------------------------------------------
// assign compact slots to candidate entities (CAS dedup; order-free)
// ---------------------------------------------------------------------------
__global__ void k_assign(const int* __restrict__ ctx, const int* __restrict__ entity_ids) {
    int t = blockIdx.x * blockDim.x + threadIdx.x;
    if (t >= NCAND) return;
    int id = (t < B_USERS * L_CTX) ? ctx[t] : entity_ids[t - B_USERS * L_CTX];
    if (atomicCAS(&g_slot[id], -1, -2) == -1) {
        int s = atomicAdd(&g_M, 1);
        g_ent[s] = id;
        g_slot[id] = s;
    }
}

// ---------------------------------------------------------------------------
// edge pass 1: hist + degree for edges into needed dsts
// ---------------------------------------------------------------------------
__global__ void k_epass1(const int* __restrict__ edge_index, const int* __restrict__ edge_type) {
    int e = blockIdx.x * blockDim.x + threadIdx.x;
    if (e >= E_EDGES) return;
    int dst = edge_index[E_EDGES + e];
    int s = g_slot[dst];
    if (s < 0) return;
    int rel = edge_type[e];
    atomicAdd(&g_hist2[s], 1);
    atomicAdd(&g_deg2[s * N_REL + rel], 1);
}

// ---------------------------------------------------------------------------
// slot-edge scan: 1 block, 1024 threads, 4 elems each; warp-shuffle 2-level
// ---------------------------------------------------------------------------
__global__ void __launch_bounds__(1024) k_escan() {
    __shared__ int wsum[32];
    int t = threadIdx.x, lane = t & 31, wid = t >> 5;
    int v[4]; int sum = 0;
#pragma unroll
    for (int j = 0; j < 4; j++) { v[j] = g_hist2[t * 4 + j]; sum += v[j]; }
    // inclusive warp scan of per-thread sums
    int s = sum;
#pragma unroll
    for (int o = 1; o < 32; o <<= 1) {
        int a = __shfl_up_sync(0xFFFFFFFFu, s, o);
        if (lane >= o) s += a;
    }
    if (lane == 31) wsum[wid] = s;
    __syncthreads();
    if (wid == 0) {
        int ws = wsum[lane];
#pragma unroll
        for (int o = 1; o < 32; o <<= 1) {
            int a = __shfl_up_sync(0xFFFFFFFFu, ws, o);
            if (lane >= o) ws += a;
        }
        wsum[lane] = ws;
    }
    __syncthreads();
    int base = ((wid > 0) ? wsum[wid - 1] : 0) + s - sum;   // exclusive prefix
#pragma unroll
    for (int j = 0; j < 4; j++) {
        g_eoff[t * 4 + j] = base;
        g_cur2[t * 4 + j] = base;
        base += v[j];
    }
    if (t == 1023) g_eoff[MMAX] = base;
}

// ---------------------------------------------------------------------------
// edge pass 2: scatter relevant edges into slot-sorted order
// ---------------------------------------------------------------------------
__global__ void k_epass2(const int* __restrict__ edge_index, const int* __restrict__ edge_type) {
    int e = blockIdx.x * blockDim.x + threadIdx.x;
    if (e >= E_EDGES) return;
    int dst = edge_index[E_EDGES + e];
    int s = g_slot[dst];
    if (s < 0) return;
    int src = edge_index[e];
    int rel = edge_type[e];
    int pos = atomicAdd(&g_cur2[s], 1);
    g_elist[pos] = src | (rel << 17);       // src < 2^17, rel < 2^6
}

// ---------------------------------------------------------------------------
// aggregation: warp per needed slot; gather basis rows directly.
// kg = root + bias + sum_edges norm * sum_b comp[rel,b] * basis[b][src]
// ---------------------------------------------------------------------------
__global__ void __launch_bounds__(256) k_agg(const float* __restrict__ basis,
                                             const float* __restrict__ comp,
                                             const float* __restrict__ root,
                                             const float* __restrict__ bias) {
    __shared__ float s_comp[N_REL * NBASES];
    for (int i = threadIdx.x; i < N_REL * NBASES; i += blockDim.x) s_comp[i] = comp[i];
    __syncthreads();

    int slot = (blockIdx.x * blockDim.x + threadIdx.x) >> 5;
    int lane = threadIdx.x & 31;
    if (slot >= g_M) return;

    int ent = g_ent[slot];
    float4 acc = reinterpret_cast<const float4*>(root)[(size_t)ent * 32 + lane];
    float4 bv  = reinterpret_cast<const float4*>(bias)[lane];
    acc.x += bv.x; acc.y += bv.y; acc.z += bv.z; acc.w += bv.w;

    int n0 = g_eoff[slot], n1 = g_eoff[slot + 1];
    for (int i = n0; i < n1; i++) {
        int packed = g_elist[i];                 // warp-broadcast load
        int src = packed & 0x1FFFF;
        int rel = packed >> 17;
        float norm = 1.0f / (float)max(g_deg2[slot * N_REL + rel], 1);
        const float* c = s_comp + rel * NBASES;
        const float4* bp = reinterpret_cast<const float4*>(basis) + (size_t)src * 32 + lane;
        float4 br[NBASES];
#pragma unroll
        for (int b = 0; b < NBASES; b++) br[b] = bp[(size_t)b * (N_ENTITY * 32)];
        float4 m;
        m.x = c[0] * br[0].x; m.y = c[0] * br[0].y; m.z = c[0] * br[0].z; m.w = c[0] * br[0].w;
#pragma unroll
        for (int b = 1; b < NBASES; b++) {
            float cb = c[b];
            m.x += cb * br[b].x; m.y += cb * br[b].y; m.z += cb * br[b].z; m.w += cb * br[b].w;
        }
        acc.x += norm * m.x; acc.y += norm * m.y; acc.z += norm * m.z; acc.w += norm * m.w;
    }
    reinterpret_cast<float4*>(g_kgc)[(size_t)slot * 32 + lane] = acc;
}

// ---------------------------------------------------------------------------
// per-slot attention score; attn_W staged through smem in 32-row tiles.
// block = 8 warps, each warp owns one slot; grid covers MMAX/8 slots.
//   g_sent[slot] = sum_d tanh((kgc[slot] @ W)[d]) * ab[d]
// ---------------------------------------------------------------------------
#define SC_WARPS 8
__global__ void __launch_bounds__(SC_WARPS * 32) k_score(const float* __restrict__ attn_W,
                                                         const float* __restrict__ attn_b) {
    __shared__ float sW[32 * DDIM];     // 16 KB tile
    int t = threadIdx.x;
    int lane = t & 31, wid = t >> 5;
    int slot = blockIdx.x * SC_WARPS + wid;     // < MMAX by grid construction
    bool active = slot < g_M;

    float4 h4 = make_float4(0.f, 0.f, 0.f, 0.f);
    if (active)
        h4 = reinterpret_cast<const float4*>(g_kgc + (size_t)slot * DDIM)[lane];

    float u0 = 0.f, u1 = 0.f, u2 = 0.f, u3 = 0.f;
#pragma unroll
    for (int tile = 0; tile < DDIM / 32; tile++) {
        __syncthreads();
        for (int i = t; i < 32 * DDIM; i += SC_WARPS * 32)
            sW[i] = attn_W[tile * 32 * DDIM + i];
        __syncthreads();
#pragma unroll 4
        for (int kk = 0; kk < 32; kk++) {
            int k = tile * 32 + kk;
            int sl = k >> 2, cp = k & 3;
            float hv = (cp == 0) ? h4.x : (cp == 1) ? h4.y : (cp == 2) ? h4.z : h4.w;
            float hk = __shfl_sync(0xFFFFFFFFu, hv, sl);
            const float* wr = sW + kk * DDIM;
            u0 += hk * wr[lane];
            u1 += hk * wr[lane + 32];
            u2 += hk * wr[lane + 64];
            u3 += hk * wr[lane + 96];
        }
    }
    if (active) {
        float acc = tanhf(u0) * attn_b[lane] + tanhf(u1) * attn_b[lane + 32]
                  + tanhf(u2) * attn_b[lane + 64] + tanhf(u3) * attn_b[lane + 96];
#pragma unroll
        for (int o = 16; o; o >>= 1) acc += __shfl_xor_sync(0xFFFFFFFFu, acc, o);
        if (lane == 0) g_sent[slot] = acc;
    }
}

// ---------------------------------------------------------------------------
// fused output kernel: blocks [0,64) = users, [64,320) = entities
// ---------------------------------------------------------------------------
__global__ void __launch_bounds__(DDIM) k_out(const int* __restrict__ ctx,
                       const int* __restrict__ cmask,
                       const int* __restrict__ entity_ids,
                       const float* __restrict__ fc1_W, const float* __restrict__ fc1_b,
                       const float* __restrict__ fc2_W, const float* __restrict__ fc2_b,
                       const float* __restrict__ efc1_W, const float* __restrict__ efc1_b,
                       const float* __restrict__ efc2_W, const float* __restrict__ efc2_b,
                       float* __restrict__ out) {
    __shared__ float xin[DDIM];
    __shared__ float yv[DDIM];
    __shared__ float attn[L_CTX];
    int t = threadIdx.x;

    const float *W1, *b1, *W2, *b2;
    float* dst;

    if (blockIdx.x < B_USERS) {
        int b = blockIdx.x;
        if (t == 0) {
            float mx = -3.4e38f; bool any = false;
            float scl[L_CTX];
            for (int l = 0; l < L_CTX; l++) {
                scl[l] = g_sent[g_slot[ctx[b * L_CTX + l]]];
                if (cmask[b * L_CTX + l]) { any = true; mx = fmaxf(mx, scl[l]); }
            }
            float s = 0.f;
            for (int l = 0; l < L_CTX; l++) {
                float v = cmask[b * L_CTX + l] ? expf(scl[l] - mx) : 0.f;
                attn[l] = v; s += v;
            }
            float inv = any ? 1.f / s : 0.f;
            for (int l = 0; l < L_CTX; l++) attn[l] *= inv;
        }
        __syncthreads();
        // L_CTX = 50 is even: the pair loop covers all l (no tail)
        float r0 = 0.f, r1 = 0.f;
        for (int l = 0; l < L_CTX; l += 2) {
            int s0 = g_slot[ctx[b * L_CTX + l]];
            int s1 = g_slot[ctx[b * L_CTX + l + 1]];
            r0 += attn[l]     * g_kgc[(size_t)s0 * DDIM + t];
            r1 += attn[l + 1] * g_kgc[(size_t)s1 * DDIM + t];
        }
        xin[t] = r0 + r1;
        W1 = fc1_W; b1 = fc1_b; W2 = fc2_W; b2 = fc2_b;
        dst = out + b * DDIM;
    } else {
        int i = blockIdx.x - B_USERS;
        int slot = g_slot[entity_ids[i]];
        xin[t] = g_kgc[(size_t)slot * DDIM + t];
        W1 = efc1_W; b1 = efc1_b; W2 = efc2_W; b2 = efc2_b;
        dst = out + B_USERS * DDIM + i * DDIM;
    }
    __syncthreads();

    float y0 = 0.f, y1 = 0.f, y2 = 0.f, y3 = 0.f;
#pragma unroll 4
    for (int k = 0; k < DDIM; k += 4) {
        y0 += xin[k]     * W1[(k)     * DDIM + t];
        y1 += xin[k + 1] * W1[(k + 1) * DDIM + t];
        y2 += xin[k + 2] * W1[(k + 2) * DDIM + t];
        y3 += xin[k + 3] * W1[(k + 3) * DDIM + t];
    }
    yv[t] = fmaxf(b1[t] + (y0 + y1) + (y2 + y3), 0.f);
    __syncthreads();

    float o0 = 0.f, o1 = 0.f, o2 = 0.f, o3 = 0.f;
#pragma unroll 4
    for (int k = 0; k < DDIM; k += 4) {
        o0 += yv[k]     * W2[(k)     * DDIM + t];
        o1 += yv[k + 1] * W2[(k + 1) * DDIM + t];
        o2 += yv[k + 2] * W2[(k + 2) * DDIM + t];
        o3 += yv[k + 3] * W2[(k + 3) * DDIM + t];
    }
    dst[t] = b2[t] + (o0 + o1) + (o2 + o3);
}

// ---------------------------------------------------------------------------
extern "C" void kernel_launch(void* const* d_in, const int* in_sizes, int n_in,
                              void* d_out, int out_size) {
    const int*   edge_index = (const int*)d_in[0];
    const int*   edge_type  = (const int*)d_in[1];
    const int*   ctx        = (const int*)d_in[2];
    const int*   cmask      = (const int*)d_in[3];
    const int*   entity_ids = (const int*)d_in[4];
    const float* comp       = (const float*)d_in[5];
    const float* basis      = (const float*)d_in[6];
    const float* root       = (const float*)d_in[7];
    const float* bias       = (const float*)d_in[8];
    const float* attn_W     = (const float*)d_in[9];
    const float* attn_b     = (const float*)d_in[10];
    const float* fc1_W      = (const float*)d_in[11];
    const float* fc1_b      = (const float*)d_in[12];
    const float* fc2_W      = (const float*)d_in[13];
    const float* fc2_b      = (const float*)d_in[14];
    const float* efc1_W     = (const float*)d_in[15];
    const float* efc1_b     = (const float*)d_in[16];
    const float* efc2_W     = (const float*)d_in[17];
    const float* efc2_b     = (const float*)d_in[18];
    float* out = (float*)d_out;

    k_setup<<<256, 256>>>();
    k_assign<<<(NCAND + 255) / 256, 256>>>(ctx, entity_ids);
    k_epass1<<<(E_EDGES + 255) / 256, 256>>>(edge_index, edge_type);
    k_escan<<<1, 1024>>>();
    k_epass2<<<(E_EDGES + 255) / 256, 256>>>(edge_index, edge_type);
    k_agg<<<(MMAX * 32) / 256, 256>>>(basis, comp, root, bias);
    k_score<<<MMAX / SC_WARPS, SC_WARPS * 32>>>(attn_W, attn_b);
    k_out<<<B_USERS + NE_ENT, DDIM>>>(ctx, cmask, entity_ids,
                                      fc1_W, fc1_b, fc2_W, fc2_b,
                                      efc1_W, efc1_b, efc2_W, efc2_b, out);
}